// round 11
// baseline (speedup 1.0000x reference)
#include <cuda_runtime.h>
#include <math.h>

// Problem constants
#define BB 16
#define HH 384
#define WW 512
#define CC 3
#define HW (HH * WW)
#define NPIX (BB * HW)

// Gather tiling: warp covers 16 wide x 4 tall; block = 8 warps = 16 wide x 32 tall
#define TILE_W 16
#define TILE_H 32

// Per-batch precomputed transform: p = d * (N @ [u,v,1]) + T
__device__ float g_M[BB][12];

// ---------------------------------------------------------------------------
// Kernel 1: pose matrices (tiny)
// ---------------------------------------------------------------------------
__global__ void pose_kernel(const float* __restrict__ pose,
                            const float* __restrict__ K) {
    int b = threadIdx.x;
    if (b >= BB) return;

    float tx = pose[b * 6 + 0] * 0.01f;
    float ty = pose[b * 6 + 1] * 0.01f;
    float tz = pose[b * 6 + 2] * 0.01f;
    float rx = pose[b * 6 + 3] * 0.001f;
    float ry = pose[b * 6 + 4] * 0.001f;
    float rz = pose[b * 6 + 5] * 0.001f;

    float cx = cosf(rx), sx = sinf(rx);
    float cy = cosf(ry), sy = sinf(ry);
    float cz = cosf(rz), sz = sinf(rz);

    // R = Rz @ Ry @ Rx
    float Rzy[9];
    Rzy[0] = cz * cy;  Rzy[1] = -sz;  Rzy[2] = cz * sy;
    Rzy[3] = sz * cy;  Rzy[4] = cz;   Rzy[5] = sz * sy;
    Rzy[6] = -sy;      Rzy[7] = 0.f;  Rzy[8] = cy;
    float R[9];
    R[0] = Rzy[0];
    R[1] = Rzy[1] * cx + Rzy[2] * sx;
    R[2] = -Rzy[1] * sx + Rzy[2] * cx;
    R[3] = Rzy[3];
    R[4] = Rzy[4] * cx + Rzy[5] * sx;
    R[5] = -Rzy[4] * sx + Rzy[5] * cx;
    R[6] = Rzy[6];
    R[7] = Rzy[7] * cx + Rzy[8] * sx;
    R[8] = -Rzy[7] * sx + Rzy[8] * cx;

    float k00 = K[0], k01 = K[1], k02 = K[2];
    float k10 = K[3], k11 = K[4], k12 = K[5];
    float k20 = K[6], k21 = K[7], k22 = K[8];

    float c00 = k11 * k22 - k12 * k21;
    float c01 = k12 * k20 - k10 * k22;
    float c02 = k10 * k21 - k11 * k20;
    float det = k00 * c00 + k01 * c01 + k02 * c02;
    float id = 1.0f / det;
    float Ki[9];
    Ki[0] = c00 * id;
    Ki[1] = (k02 * k21 - k01 * k22) * id;
    Ki[2] = (k01 * k12 - k02 * k11) * id;
    Ki[3] = c01 * id;
    Ki[4] = (k00 * k22 - k02 * k20) * id;
    Ki[5] = (k02 * k10 - k00 * k12) * id;
    Ki[6] = c02 * id;
    Ki[7] = (k01 * k20 - k00 * k21) * id;
    Ki[8] = (k00 * k11 - k01 * k10) * id;

    float M33[9], Mt[3];
    #pragma unroll
    for (int i = 0; i < 3; i++) {
        float a0 = (i == 0) ? k00 : (i == 1) ? k10 : k20;
        float a1 = (i == 0) ? k01 : (i == 1) ? k11 : k21;
        float a2 = (i == 0) ? k02 : (i == 1) ? k12 : k22;
        #pragma unroll
        for (int j = 0; j < 3; j++)
            M33[i * 3 + j] = a0 * R[j] + a1 * R[3 + j] + a2 * R[6 + j];
        Mt[i] = a0 * tx + a1 * ty + a2 * tz;
    }

    #pragma unroll
    for (int i = 0; i < 3; i++) {
        #pragma unroll
        for (int j = 0; j < 3; j++) {
            g_M[b][i * 3 + j] = M33[i * 3 + 0] * Ki[j]
                              + M33[i * 3 + 1] * Ki[3 + j]
                              + M33[i * 3 + 2] * Ki[6 + j];
        }
        g_M[b][9 + i] = Mt[i];
    }
}

// ---------------------------------------------------------------------------
// Kernel 2: fused warp + bilinear gather DIRECTLY from fp32 NHWC source.
// 2 px/thread, 2-D warp tiles (16x4). Pixels processed as two sequential
// 12-load groups to bound register pressure while keeping 12-deep MLP.
// Grid: (W/TILE_W, H/TILE_H, B)
// ---------------------------------------------------------------------------
__device__ __forceinline__ void sample_px(
    const float* __restrict__ base3,  // src + b*HW*3
    float xs, float ys, float* o)
{
    float x0f = floorf(xs), y0f = floorf(ys);
    float fx = xs - x0f, fy = ys - y0f;
    float gx = 1.0f - fx, gy = 1.0f - fy;
    float wa = gx * gy;
    float wb = gx * fy;
    float wc = fx * gy;
    float wd = fx * fy;

    int x0 = (int)fminf(fmaxf(x0f, 0.0f), (float)(WW - 1));
    int x1 = (int)fminf(fmaxf(x0f + 1.0f, 0.0f), (float)(WW - 1));
    int y0 = (int)fminf(fmaxf(y0f, 0.0f), (float)(HH - 1));
    int y1 = (int)fminf(fmaxf(y0f + 1.0f, 0.0f), (float)(HH - 1));

    const float* pa = base3 + (y0 * WW + x0) * 3;
    const float* pc = base3 + (y0 * WW + x1) * 3;
    const float* pb = base3 + (y1 * WW + x0) * 3;
    const float* pd = base3 + (y1 * WW + x1) * 3;

    // 12 independent scalar loads issued back-to-back
    float a0 = __ldg(&pa[0]), a1 = __ldg(&pa[1]), a2 = __ldg(&pa[2]);
    float c0 = __ldg(&pc[0]), c1 = __ldg(&pc[1]), c2 = __ldg(&pc[2]);
    float b0 = __ldg(&pb[0]), b1 = __ldg(&pb[1]), b2 = __ldg(&pb[2]);
    float d0 = __ldg(&pd[0]), d1 = __ldg(&pd[1]), d2 = __ldg(&pd[2]);

    o[0] = fmaf(wa, a0, fmaf(wb, b0, fmaf(wc, c0, wd * d0)));
    o[1] = fmaf(wa, a1, fmaf(wb, b1, fmaf(wc, c1, wd * d1)));
    o[2] = fmaf(wa, a2, fmaf(wb, b2, fmaf(wc, c2, wd * d2)));
}

__global__ void __launch_bounds__(256) warp_kernel(
    const float* __restrict__ src,
    const float* __restrict__ depth,
    float* __restrict__ out)
{
    int lane = threadIdx.x & 31;
    int warp = threadIdx.x >> 5;
    int b = blockIdx.z;

    // warp tile: 16 wide x 4 tall; 8 lanes per row, 2px per lane
    int row_in_warp = lane >> 3;        // 0..3
    int col8 = lane & 7;                // 0..7
    int v = blockIdx.y * TILE_H + warp * 4 + row_in_warp;
    int u0 = blockIdx.x * TILE_W + col8 * 2;

    int pix0 = b * HW + v * WW + u0;

    const float* M = g_M[b];
    float n00 = M[0], n01 = M[1], n02 = M[2];
    float n10 = M[3], n11 = M[4], n12 = M[5];
    float n20 = M[6], n21 = M[7], n22 = M[8];
    float t0  = M[9], t1  = M[10], t2 = M[11];

    float2 dv = __ldg((const float2*)&depth[pix0]);
    float vf = (float)v;
    float rx_ = fmaf(n01, vf, n02);
    float ry_ = fmaf(n11, vf, n12);
    float rz_ = fmaf(n21, vf, n22);

    const float* base3 = src + (size_t)b * HW * 3;

    float o[6];

    #pragma unroll
    for (int j = 0; j < 2; j++) {
        float d = (j == 0) ? dv.x : dv.y;
        float uf = (float)(u0 + j);
        float px = fmaf(d, fmaf(n00, uf, rx_), t0);
        float py = fmaf(d, fmaf(n10, uf, ry_), t1);
        float pz = fmaf(d, fmaf(n20, uf, rz_), t2);
        float inv_z = 1.0f / (pz + 1e-10f);
        sample_px(base3, px * inv_z, py * inv_z, &o[3 * j]);
    }

    // 6 contiguous floats at out + pix0*3 (8B-aligned since pix0 even)
    float2* ov = (float2*)(out + (size_t)pix0 * CC);
    ov[0] = make_float2(o[0], o[1]);
    ov[1] = make_float2(o[2], o[3]);
    ov[2] = make_float2(o[4], o[5]);
}

extern "C" void kernel_launch(void* const* d_in, const int* in_sizes, int n_in,
                              void* d_out, int out_size) {
    const float* src   = (const float*)d_in[0];   // [B,H,W,C]
    const float* depth = (const float*)d_in[1];   // [B,H,W]
    const float* pose  = (const float*)d_in[2];   // [B,6]
    const float* K     = (const float*)d_in[3];   // [3,3]
    float* out = (float*)d_out;

    pose_kernel<<<1, 32>>>(pose, K);

    dim3 gat_grid(WW / TILE_W, HH / TILE_H, BB);   // 32 x 12 x 16 = 6144
    warp_kernel<<<gat_grid, 256>>>(src, depth, out);
}